// round 16
// baseline (speedup 1.0000x reference)
#include <cuda_runtime.h>
#include <cuda_bf16.h>
#include <cuda_fp16.h>
#include <cstdint>
#include <math.h>

// Problem constants
#define BB 4
#define SSEQ 4096
#define HH 8
#define DI 128
#define DOUT 128
#define HD 1024            // HH*DI
#define NTOK (BB*SSEQ)     // 16384
#define CHS 32             // scan / cumsum chunk length
#define NCHS 128           // SSEQ / CHS

// ---------------- scratch (static device globals; no allocations) -------------
__device__ __half  g_h3h[(long)NTOK * HH * 384];  // h3 raw (fp16); reused as og
__device__ __half2 g_gates[(long)NTOK * HD];      // (fg, igh) packed fp16
__device__ float g_cell[(long)NTOK * HD];    // scan output (fp32)
__device__ float g_ctot[NCHS * BB * HD];     // [chunk][b][hd] cumsum chunk totals
__device__ float g_coff[NCHS * BB * HD];     // exclusive chunk offsets
__device__ float g_aggF[NCHS * BB * HD];
__device__ float g_aggI[NCHS * BB * HD];
__device__ float g_carry[NCHS * BB * HD];
__device__ float2 g_stat[NTOK];              // (mu, rs) of csum-LN per token

// bf16 hi/lo split weights, K-major ([head][n][k])
__device__ __nv_bfloat16 g_Wh_hi[8 * 384 * 256];
__device__ __nv_bfloat16 g_Wh_lo[8 * 384 * 256];
__device__ __nv_bfloat16 g_Wo_hi[8 * 128 * 256];
__device__ __nv_bfloat16 g_Wo_lo[8 * 128 * 256];

// fast sigmoid via HW tanh: sigmoid(x) = 0.5*tanh(x/2)+0.5
__device__ __forceinline__ float sigmoidf_(float x) {
    float t;
    asm("tanh.approx.f32 %0, %1;" : "=f"(t) : "f"(0.5f * x));
    return fmaf(0.5f, t, 0.5f);
}

// ======================= mma.sync / ldmatrix helpers ==========================
__device__ __forceinline__ uint32_t s2u(const void* p) {
    uint32_t a;
    asm("{ .reg .u64 t; cvta.to.shared.u64 t, %1; cvt.u32.u64 %0, t; }" : "=r"(a) : "l"(p));
    return a;
}
__device__ __forceinline__ void ldsm4(uint32_t r[4], uint32_t addr) {
    asm volatile("ldmatrix.sync.aligned.m8n8.x4.shared.b16 {%0,%1,%2,%3}, [%4];"
                 : "=r"(r[0]), "=r"(r[1]), "=r"(r[2]), "=r"(r[3]) : "r"(addr));
}
__device__ __forceinline__ void mma16816(float* c, const uint32_t* a, const uint32_t* b) {
    asm volatile(
        "mma.sync.aligned.m16n8k16.row.col.f32.bf16.bf16.f32 "
        "{%0,%1,%2,%3}, {%4,%5,%6,%7}, {%8,%9}, {%0,%1,%2,%3};"
        : "+f"(c[0]), "+f"(c[1]), "+f"(c[2]), "+f"(c[3])
        : "r"(a[0]), "r"(a[1]), "r"(a[2]), "r"(a[3]), "r"(b[0]), "r"(b[1]));
}

// block-wide sum reduction (blockDim.x == 256), result broadcast
__device__ __forceinline__ float blockSum256(float v, float* red) {
    int tid = threadIdx.x;
    #pragma unroll
    for (int o = 16; o; o >>= 1) v += __shfl_xor_sync(0xffffffffu, v, o);
    if ((tid & 31) == 0) red[tid >> 5] = v;
    __syncthreads();
    if (tid < 32) {
        float x = (tid < 8) ? red[tid] : 0.0f;
        #pragma unroll
        for (int o = 4; o; o >>= 1) x += __shfl_xor_sync(0xffffffffu, x, o);
        if (tid == 0) red[0] = x;
    }
    __syncthreads();
    float r = red[0];
    __syncthreads();
    return r;
}

// fused (sum, sumsq) block reduction, result broadcast
__device__ __forceinline__ float2 blockSum2(float2 v, float2* red) {
    int tid = threadIdx.x;
    #pragma unroll
    for (int o = 16; o; o >>= 1) {
        v.x += __shfl_xor_sync(0xffffffffu, v.x, o);
        v.y += __shfl_xor_sync(0xffffffffu, v.y, o);
    }
    if ((tid & 31) == 0) red[tid >> 5] = v;
    __syncthreads();
    if (tid < 32) {
        float2 x = (tid < 8) ? red[tid] : make_float2(0.f, 0.f);
        #pragma unroll
        for (int o = 4; o; o >>= 1) {
            x.x += __shfl_xor_sync(0xffffffffu, x.x, o);
            x.y += __shfl_xor_sync(0xffffffffu, x.y, o);
        }
        if (tid == 0) red[0] = x;
    }
    __syncthreads();
    float2 r = red[0];
    __syncthreads();
    return r;
}

// ---------------- K0: fused weight prep + cumsum chunk totals -----------------
__global__ __launch_bounds__(256) void k_prep(const float* __restrict__ W1,
                                              const float* __restrict__ W2,
                                              const float* __restrict__ hi) {
    if (blockIdx.x < 512) {
        int b = blockIdx.x >> 7, chunk = blockIdx.x & 127;
        int hd = threadIdx.x * 4;
        long base = ((long)(b * SSEQ + chunk * CHS)) * HD + hd;
        float4 run = make_float4(0.f, 0.f, 0.f, 0.f);
        #pragma unroll
        for (int i0 = 0; i0 < CHS; i0 += 4) {
            float4 v0 = *(const float4*)(hi + base + (long)(i0 + 0) * HD);
            float4 v1 = *(const float4*)(hi + base + (long)(i0 + 1) * HD);
            float4 v2 = *(const float4*)(hi + base + (long)(i0 + 2) * HD);
            float4 v3 = *(const float4*)(hi + base + (long)(i0 + 3) * HD);
            run.x += v0.x + v1.x + v2.x + v3.x;
            run.y += v0.y + v1.y + v2.y + v3.y;
            run.z += v0.z + v1.z + v2.z + v3.z;
            run.w += v0.w + v1.w + v2.w + v3.w;
        }
        *(float4*)(g_ctot + (chunk * BB + b) * HD + hd) = run;
        return;
    }
    int gid = (blockIdx.x - 512) * 256 + threadIdx.x;
    if (gid < 8 * 256 * 384) {                 // W_hid (8,256,384)
        int n = gid % 384;
        int hk = gid / 384;
        int k = hk & 255;
        int h = hk >> 8;
        float v = W1[gid];
        __nv_bfloat16 hh = __float2bfloat16_rn(v);
        __nv_bfloat16 ll = __float2bfloat16_rn(v - __bfloat162float(hh));
        int o = (h * 384 + n) * 256 + k;
        g_Wh_hi[o] = hh;
        g_Wh_lo[o] = ll;
    } else {                                   // W_og (8,256,128)
        int g2 = gid - 8 * 256 * 384;
        int n = g2 & 127;
        int k = (g2 >> 7) & 255;
        int h = g2 >> 15;
        float v = W2[g2];
        __nv_bfloat16 hh = __float2bfloat16_rn(v);
        __nv_bfloat16 ll = __float2bfloat16_rn(v - __bfloat162float(hh));
        int o = (h * 128 + n) * 256 + k;
        g_Wo_hi[o] = hh;
        g_Wo_lo[o] = ll;
    }
}

// ---------------- K1: scan chunk totals -> exclusive offsets ------------------
__global__ __launch_bounds__(256) void k_scanoff() {
    int gid = blockIdx.x * 256 + threadIdx.x;   // 0..1023
    int b = gid >> 8;
    int hd = (gid & 255) * 4;
    float4 run = make_float4(0.f, 0.f, 0.f, 0.f);
    #pragma unroll 8
    for (int c = 0; c < NCHS; c++) {
        float4 t = *(const float4*)(g_ctot + (c * BB + b) * HD + hd);
        *(float4*)(g_coff + (c * BB + b) * HD + hd) = run;
        run.x += t.x; run.y += t.y; run.z += t.z; run.w += t.w;
    }
}

// ---------------- K2: csum-LN stats (mu, rs) per token, reduce-only -----------
__global__ __launch_bounds__(256) void k_stats1(const float* __restrict__ hi) {
    __shared__ float red[32];
    int b = blockIdx.x >> 7, chunk = blockIdx.x & 127;
    int hd = threadIdx.x * 4;
    long base = ((long)(b * SSEQ + chunk * CHS)) * HD + hd;
    float4 run = *(const float4*)(g_coff + (chunk * BB + b) * HD + hd);
    for (int i = 0; i < CHS; i++) {
        float4 v = *(const float4*)(hi + base + (long)i * HD);
        float s = run.x + run.y + run.z + run.w;
        s = blockSum256(s, red);
        float mu = s * (1.0f / 1024.0f);
        float dx = run.x - mu, dy = run.y - mu, dz = run.z - mu, dw = run.w - mu;
        float q = dx * dx + dy * dy + dz * dz + dw * dw;
        q = blockSum256(q, red);
        if (threadIdx.x == 0) {
            float rs = rsqrtf(q * (1.0f / 1024.0f) + 1e-6f);
            g_stat[b * SSEQ + chunk * CHS + i] = make_float2(mu, rs);
        }
        run.x += v.x; run.y += v.y; run.z += v.z; run.w += v.w;
    }
}

// ---------------- GEMM common geometry ----------------------------------------
#define GA_BYTES (64 * 264 * 2)          // 33792 per A tile
#define GB_BYTES (128 * 72 * 2)          // 18432 per B tile
#define SM_AHI  0
#define SM_ALO  (GA_BYTES)
#define SM_BHI  (2 * GA_BYTES)
#define SM_BLO  (2 * GA_BYTES + GB_BYTES)
#define SM_GEMM (2 * GA_BYTES + 2 * GB_BYTES)  // 104448

// MMA mainloop + epilogue (fp16 output) shared by both GEMMs (A already in SMEM)
__device__ __forceinline__ void gemm_core(
    char* sm, uint32_t sb, int tid,
    const __nv_bfloat16* __restrict__ Whi, const __nv_bfloat16* __restrict__ Wlo,
    const float* __restrict__ bias, __half* __restrict__ out,
    int Nw, int nTiles, int head, int tok0)
{
    int wid = tid >> 5, lid = tid & 31;
    int warp_m = wid >> 2, warp_n = wid & 3;
    int sub = lid >> 3, rin = lid & 7;

    for (int nt = 0; nt < nTiles; nt++) {
        int n0 = nt * 128;
        float acc[2][4][4];
        #pragma unroll
        for (int i = 0; i < 2; i++)
            #pragma unroll
            for (int j = 0; j < 4; j++)
                #pragma unroll
                for (int e = 0; e < 4; e++) acc[i][j][e] = 0.0f;

        for (int c = 0; c < 4; c++) {
            #pragma unroll
            for (int g = tid; g < 1024; g += 256) {
                int n = g >> 3, q = g & 7;
                long gb = (long)(head * Nw + n0 + n) * 256 + c * 64 + q * 8;
                uint4 vh = *(const uint4*)(Whi + gb);
                uint4 vl = *(const uint4*)(Wlo + gb);
                int off = n * 144 + q * 16;
                *(uint4*)(sm + SM_BHI + off) = vh;
                *(uint4*)(sm + SM_BLO + off) = vl;
            }
            __syncthreads();

            #pragma unroll
            for (int s = 0; s < 4; s++) {
                uint32_t Bh[4][2], Bl[4][2];
                #pragma unroll
                for (int p = 0; p < 2; p++) {
                    int brow = warp_n * 32 + p * 16 + rin + ((sub >> 1) << 3);
                    int bk = s * 16 + ((sub & 1) << 3);
                    uint32_t addr = sb + SM_BHI + brow * 144 + bk * 2;
                    uint32_t t4[4];
                    ldsm4(t4, addr);
                    Bh[2 * p][0] = t4[0]; Bh[2 * p][1] = t4[1];
                    Bh[2 * p + 1][0] = t4[2]; Bh[2 * p + 1][1] = t4[3];
                    ldsm4(t4, addr + (SM_BLO - SM_BHI));
                    Bl[2 * p][0] = t4[0]; Bl[2 * p][1] = t4[1];
                    Bl[2 * p + 1][0] = t4[2]; Bl[2 * p + 1][1] = t4[3];
                }
                #pragma unroll
                for (int mi = 0; mi < 2; mi++) {
                    int arow = warp_m * 32 + mi * 16 + rin + ((sub & 1) << 3);
                    int ak = c * 64 + s * 16 + ((sub >> 1) << 3);
                    uint32_t addr = sb + SM_AHI + arow * 528 + ak * 2;
                    uint32_t Ah[4], Al[4];
                    ldsm4(Ah, addr);
                    ldsm4(Al, addr + (SM_ALO - SM_AHI));
                    #pragma unroll
                    for (int ni = 0; ni < 4; ni++) {
                        mma16816(acc[mi][ni], Ah, Bh[ni]);
                        mma16816(acc[mi][ni], Ah, Bl[ni]);
                        mma16816(acc[mi][ni], Al, Bh[ni]);
                    }
                }
            }
            __syncthreads();
        }

        int g4 = lid >> 2, tg = lid & 3;
        #pragma unroll
        for (int mi = 0; mi < 2; mi++) {
            int r0 = tok0 + warp_m * 32 + mi * 16 + g4;
            #pragma unroll
            for (int ni = 0; ni < 4; ni++) {
                int ncol = n0 + warp_n * 32 + ni * 8 + tg * 2;
                float b0 = bias[head * Nw + ncol];
                float b1 = bias[head * Nw + ncol + 1];
                __half2 o0 = __floats2half2_rn(acc[mi][ni][0] + b0, acc[mi][ni][1] + b1);
                __half2 o1 = __floats2half2_rn(acc[mi][ni][2] + b0, acc[mi][ni][3] + b1);
                *(__half2*)(out + ((long)r0 * 8 + head) * Nw + ncol) = o0;
                *(__half2*)(out + ((long)(r0 + 8) * 8 + head) * Nw + ncol) = o1;
            }
        }
    }
}

// ---------------- K3: GEMM1 with inline exclusive-cumsum + csum-LN on A2 ------
__global__ __launch_bounds__(256, 2) void k_gemm1(
    const float* __restrict__ hi,
    const float* __restrict__ gcs, const float* __restrict__ bcs,
    const __nv_bfloat16* __restrict__ Whi, const __nv_bfloat16* __restrict__ Wlo,
    const float* __restrict__ bias, __half* __restrict__ out)
{
    extern __shared__ char sm[];
    uint32_t sb = s2u(sm);
    int tid = threadIdx.x;
    int mtile = blockIdx.x, head = blockIdx.y;
    int tok0 = mtile * 64;

    // ---- A-fill: thread = (lane d, half), serial 32 tokens -------------------
    {
        int half_ = tid >> 7;           // 0..1 (token sub-chunk of 32)
        int d = tid & 127;
        int b = tok0 >> 12;
        int s0 = tok0 & (SSEQ - 1);
        int chunk = (s0 >> 5) + half_;
        int hd = head * 128 + d;
        float run = g_coff[(chunk * BB + b) * HD + hd];
        float gc = gcs[hd], bc = bcs[hd];
        int r0 = half_ * 32;
        #pragma unroll 4
        for (int rr = 0; rr < 32; rr++) {
            int row = r0 + rr;
            int tok = tok0 + row;
            float v = hi[((long)tok * 8 + head) * 128 + d];
            float2 st = g_stat[tok];
            float a2 = (run - st.x) * st.y * gc + bc;   // exclusive csum, LN'd
            run += v;
            __nv_bfloat16 h1 = __float2bfloat16_rn(v);
            __nv_bfloat16 l1 = __float2bfloat16_rn(v - __bfloat162float(h1));
            __nv_bfloat16 h2 = __float2bfloat16_rn(a2);
            __nv_bfloat16 l2 = __float2bfloat16_rn(a2 - __bfloat162float(h2));
            int off = row * 528;
            *(__nv_bfloat16*)(sm + SM_AHI + off + d * 2) = h1;
            *(__nv_bfloat16*)(sm + SM_ALO + off + d * 2) = l1;
            *(__nv_bfloat16*)(sm + SM_AHI + off + (128 + d) * 2) = h2;
            *(__nv_bfloat16*)(sm + SM_ALO + off + (128 + d) * 2) = l2;
        }
    }
    __syncthreads();
    gemm_core(sm, sb, tid, Whi, Wlo, bias, out, 384, 3, head, tok0);
}

// ---------------- K4: fused h3-LN + gates + scan chunk aggregates -------------
// CTA = (b, 32-token chunk); 256 threads; serial over tokens.
__global__ __launch_bounds__(256) void k_lnscan(const float* __restrict__ gh,
                                                const float* __restrict__ bh) {
    __shared__ float2 red2[32];
    __shared__ float smv[3072];
    int b = blockIdx.x >> 7, chunk = blockIdx.x & 127;
    int tid = threadIdx.x;
    int t0 = b * SSEQ + chunk * CHS;

    // preload gamma/beta for this thread's 4 scan lanes (hd = tid*4 .. +3)
    int hd0 = tid * 4;
    int nh = hd0 >> 7, d0 = hd0 & 127;
    float gi[4], bi[4], gf[4], bf[4], gv[4], bv[4];
    #pragma unroll
    for (int l = 0; l < 4; l++) {
        int ei = nh * 384 + d0 + l;
        gi[l] = gh[ei];       bi[l] = bh[ei];
        gf[l] = gh[ei + 128]; bf[l] = bh[ei + 128];
        gv[l] = gh[ei + 256]; bv[l] = bh[ei + 256];
    }

    float4 F = make_float4(1.f, 1.f, 1.f, 1.f);
    float4 I = make_float4(0.f, 0.f, 0.f, 0.f);

    for (int i = 0; i < CHS; i++) {
        long t = t0 + i;
        const __half2* hp = (const __half2*)(g_h3h + t * 3072);
        float2 v[6];
        float2 sq = make_float2(0.f, 0.f);
        #pragma unroll
        for (int j = 0; j < 6; j++) {
            v[j] = __half22float2(hp[tid + j * 256]);
            sq.x += v[j].x + v[j].y;
            sq.y += v[j].x * v[j].x + v[j].y * v[j].y;
        }
        float2 s = blockSum2(sq, red2);
        float mu = s.x * (1.0f / 3072.0f);
        float var = s.y * (1.0f / 3072.0f) - mu * mu;
        float rs = rsqrtf(var + 1e-6f);
        #pragma unroll
        for (int j = 0; j < 6; j++) {
            int e = (tid + j * 256) * 2;
            smv[e] = v[j].x;
            smv[e + 1] = v[j].y;
        }
        __syncthreads();
        #pragma unroll
        for (int l = 0; l < 4; l++) {
            int ei = nh * 384 + d0 + l;
            float ig = (smv[ei]       - mu) * rs * gi[l] + bi[l];
            float fg = (smv[ei + 128] - mu) * rs * gf[l] + bf[l];
            float hv = (smv[ei + 256] - mu) * rs * gv[l] + bv[l];
            float f = sigmoidf_(fg);
            float ii = sigmoidf_(ig) * fmaxf(hv, 0.0f);
            g_gates[t * HD + hd0 + l] = __floats2half2_rn(f, ii);
            float* Fp = (&F.x) + l;
            float* Ip = (&I.x) + l;
            *Ip = fmaf(f, *Ip, ii);
            *Fp *= f;
        }
        __syncthreads();
    }
    *(float4*)(g_aggF + (chunk * BB + b) * HD + hd0) = F;
    *(float4*)(g_aggI + (chunk * BB + b) * HD + hd0) = I;
}

// ---------------- K5: scan carries across chunks ------------------------------
__global__ __launch_bounds__(256) void k_scan_carry(const float* __restrict__ init_cx) {
    int gid = blockIdx.x * 256 + threadIdx.x;   // 0..1023
    int b = gid >> 8;
    int hd = (gid & 255) * 4;
    float4 c = *(const float4*)(init_cx + hd);
    #pragma unroll 8
    for (int chunk = 0; chunk < NCHS; chunk++) {
        int o = (chunk * BB + b) * HD + hd;
        *(float4*)(g_carry + o) = c;
        float4 F = *(const float4*)(g_aggF + o);
        float4 I = *(const float4*)(g_aggI + o);
        c.x = fmaf(F.x, c.x, I.x); c.y = fmaf(F.y, c.y, I.y);
        c.z = fmaf(F.z, c.z, I.z); c.w = fmaf(F.w, c.w, I.w);
    }
}

// ---------------- K6: GEMM2 with inline cell recurrence on A2 -----------------
__global__ __launch_bounds__(256, 2) void k_gemm2(
    const float* __restrict__ hi,
    const __nv_bfloat16* __restrict__ Whi, const __nv_bfloat16* __restrict__ Wlo,
    const float* __restrict__ bias, __half* __restrict__ out)
{
    extern __shared__ char sm[];
    uint32_t sb = s2u(sm);
    int tid = threadIdx.x;
    int mtile = blockIdx.x, head = blockIdx.y;
    int tok0 = mtile * 64;

    // ---- A-fill: recompute cell from gates + carry, serial 32 tokens ---------
    {
        int half_ = tid >> 7;
        int d = tid & 127;
        int b = tok0 >> 12;
        int s0 = tok0 & (SSEQ - 1);
        int chunk = (s0 >> 5) + half_;
        int hd = head * 128 + d;
        float c = g_carry[(chunk * BB + b) * HD + hd];
        int r0 = half_ * 32;
        #pragma unroll 4
        for (int rr = 0; rr < 32; rr++) {
            int row = r0 + rr;
            long tok = tok0 + row;
            float v = hi[(tok * 8 + head) * 128 + d];
            float2 fi = __half22float2(g_gates[tok * HD + hd]);
            c = fmaf(fi.x, c, fi.y);
            g_cell[tok * HD + hd] = c;
            __nv_bfloat16 h1 = __float2bfloat16_rn(v);
            __nv_bfloat16 l1 = __float2bfloat16_rn(v - __bfloat162float(h1));
            __nv_bfloat16 h2 = __float2bfloat16_rn(c);
            __nv_bfloat16 l2 = __float2bfloat16_rn(c - __bfloat162float(h2));
            int off = row * 528;
            *(__nv_bfloat16*)(sm + SM_AHI + off + d * 2) = h1;
            *(__nv_bfloat16*)(sm + SM_ALO + off + d * 2) = l1;
            *(__nv_bfloat16*)(sm + SM_AHI + off + (128 + d) * 2) = h2;
            *(__nv_bfloat16*)(sm + SM_ALO + off + (128 + d) * 2) = l2;
        }
    }
    __syncthreads();
    gemm_core(sm, sb, tid, Whi, Wlo, bias, out, 128, 1, head, tok0);
}

// ---------------- K7: final LN over (H,DO)=1024 + sigmoid * cell --------------
__global__ __launch_bounds__(256) void k_final(const float* __restrict__ gog,
                                               const float* __restrict__ bog,
                                               float* __restrict__ out) {
    __shared__ float red[32];
    int t = blockIdx.x;
    int tid = threadIdx.x;
    int e0 = tid * 4;
    float v[4];
    {
        uint2 u = *(const uint2*)(g_h3h + (long)t * HD + e0);
        __half2* hp = (__half2*)&u;
        float2 p0 = __half22float2(hp[0]);
        float2 p1 = __half22float2(hp[1]);
        v[0] = p0.x; v[1] = p0.y; v[2] = p1.x; v[3] = p1.y;
    }
    float s1 = v[0] + v[1] + v[2] + v[3];
    s1 = blockSum256(s1, red);
    float mu = s1 * (1.0f / 1024.0f);
    float q = 0.0f;
    #pragma unroll
    for (int j = 0; j < 4; j++) { float d = v[j] - mu; q += d * d; }
    q = blockSum256(q, red);
    float rs = rsqrtf(q * (1.0f / 1024.0f) + 1e-6f);
    float4 gg = *(const float4*)(gog + e0);
    float4 bb = *(const float4*)(bog + e0);
    float4 cc = *(const float4*)(g_cell + (long)t * HD + e0);
    float4 o;
    o.x = sigmoidf_((v[0] - mu) * rs * gg.x + bb.x) * cc.x;
    o.y = sigmoidf_((v[1] - mu) * rs * gg.y + bb.y) * cc.y;
    o.z = sigmoidf_((v[2] - mu) * rs * gg.z + bb.z) * cc.z;
    o.w = sigmoidf_((v[3] - mu) * rs * gg.w + bb.w) * cc.w;
    *(float4*)(out + (long)t * HD + e0) = o;
}

// ------------------------------------------------------------------------------
extern "C" void kernel_launch(void* const* d_in, const int* in_sizes, int n_in,
                              void* d_out, int out_size) {
    const float* hi        = (const float*)d_in[0];
    const float* W_hid     = (const float*)d_in[1];
    const float* b_hid     = (const float*)d_in[2];
    const float* gcsum     = (const float*)d_in[3];
    const float* bcsum     = (const float*)d_in[4];
    const float* g_hid     = (const float*)d_in[5];
    const float* beta_hid  = (const float*)d_in[6];
    const float* W_og      = (const float*)d_in[7];
    const float* b_og      = (const float*)d_in[8];
    const float* g_og      = (const float*)d_in[9];
    const float* beta_og   = (const float*)d_in[10];
    const float* init_cx   = (const float*)d_in[11];
    float* out = (float*)d_out;

    cudaFuncSetAttribute(k_gemm1, cudaFuncAttributeMaxDynamicSharedMemorySize, SM_GEMM);
    cudaFuncSetAttribute(k_gemm2, cudaFuncAttributeMaxDynamicSharedMemorySize, SM_GEMM);

    __half* h3_p;  cudaGetSymbolAddress((void**)&h3_p, g_h3h);
    __nv_bfloat16 *wh_hi, *wh_lo, *wo_hi, *wo_lo;
    cudaGetSymbolAddress((void**)&wh_hi, g_Wh_hi);
    cudaGetSymbolAddress((void**)&wh_lo, g_Wh_lo);
    cudaGetSymbolAddress((void**)&wo_hi, g_Wo_hi);
    cudaGetSymbolAddress((void**)&wo_lo, g_Wo_lo);

    k_prep<<<4608, 256>>>(W_hid, W_og, hi);              // 0
    k_scanoff<<<4, 256>>>();                             // 1
    k_stats1<<<512, 256>>>(hi);                          // 2
    k_gemm1<<<dim3(256, 8), 256, SM_GEMM>>>(hi, gcsum, bcsum, wh_hi, wh_lo,
                                            b_hid, h3_p);   // 3 <- ncu slot
    k_lnscan<<<512, 256>>>(g_hid, beta_hid);             // 4
    k_scan_carry<<<4, 256>>>(init_cx);                   // 5
    k_gemm2<<<dim3(256, 8), 256, SM_GEMM>>>(hi, wo_hi, wo_lo, b_og, h3_p); // 6
    k_final<<<NTOK, 256>>>(g_og, beta_og, out);          // 7
}